// round 17
// baseline (speedup 1.0000x reference)
#include <cuda_runtime.h>
#include <cuda_bf16.h>

// Problem geometry: [B=4, 1, D=160, H=160, W=160]
#define NB 4
#define S  160
#define PLANE4  6400               // float4/int4 per (b,d) plane
#define NCHUNKS 5120               // 8 chunks per plane, 20 rows x 40 quads
#define CHUNK4  800
#define NBLK    1280               // 5120 / 1280 = exactly 4 chunks per block
#define NT      160
#define N4      4096000            // total float4 quads
#define BATCH4  1024000            // quads per batch
#define TOTAL_ELEMS (4.0 * 160.0 * 160.0 * 160.0)

// ---- device scratch (zero at load; finalizer re-zeroes for graph replay) ---
__device__ unsigned char g_end[NB][6];  // axis-end fg proof flags [b][axis*2+side]
__device__ double g_ss8[8];             // All, D, H, W, DH, DW, HW, DHW
__device__ unsigned g_done;

// Exact f32 replication of the reference bbox math (mn<0 -> empty box).
__device__ __forceinline__ void bbox_from(int mn, int mx, int* lo, int* hi) {
    if (mn < 0) { *lo = 0; *hi = 0; return; }
    float c = ((float)mx + (float)mn) * 0.5f;
    float e = ((float)mx - (float)mn + 1.0f) * 0.5f * 1.2f;   // EXPAND
    *lo = (int)fmaxf(0.0f, floorf(c - e));
    *hi = (int)fminf((float)(S - 1), floorf(c + e));          // EXCLUSIVE
}

// Per-chunk slab bookkeeping (rare terms via shared atomics).
// sX: 0=D, 1=DH, 2=DW, 3=DHW, 4=H, 5=HW
__device__ __forceinline__ void slab_terms(int chunk, bool rg3, bool c39,
                                           float qa, float qc, float q4, float w24,
                                           float* sX) {
    const bool isRow = ((chunk & 7) == 7) && rg3;     // k=4 row is h=159
    const bool isD   = ((chunk >> 3) % S) == (S - 1); // plane d=159
    if (isRow) {
        atomicAdd(&sX[4], q4);
        if (c39) atomicAdd(&sX[5], w24);
    }
    if (isD) {
        atomicAdd(&sX[0], qa);
        if (c39) atomicAdd(&sX[2], qc);
        if (isRow) {
            atomicAdd(&sX[1], q4);
            if (c39) atomicAdd(&sX[3], w24);
        }
    }
}

// ============================================================================
// Single kernel, 1280 x 160. Each block owns EXACTLY 4 chunks (20 rows x 40
// quads each), processed as 2 pairs — each pair body front-batches 20 LDG.128
// (2 chunks x 5 rows x {pred,truth}) for deep MLP. Thread owns fixed column
// c = tid%40 and row-group rg = tid/40, so slab predicates are fixed:
//   w=159  <=> c==39 (.w lane)     h=159 <=> part==7 && rg==3 && k==4
//   d=159  <=> plane%160==159 (chunk-uniform)
// Blocks 0..23 SAMPLE 160 int4 from one (batch, axis, side) mask boundary
// region: any fg there proves that axis end (mn<=3 / mx>=156). If all 24 ends
// are proven, the reference box is exactly [0,159)^3 for every batch
// (mn<=3, mx>=156 => c-e<0, c+e>159), so the ROI complement is the three
// index-159 slabs and loss = (SS_all - 0.99*SS_out)/N with SS_out by
// inclusion-exclusion over g_ss8. Any unproven end -> exact single-block
// fallback (correct for arbitrary masks). Last-done block finalizes + resets.
// ============================================================================
__global__ __launch_bounds__(NT, 9) void k_all(const float* __restrict__ pred,
                                               const float* __restrict__ truth,
                                               const int*   __restrict__ mask,
                                               float* __restrict__ out) {
    __shared__ float  sX[6];
    __shared__ double sOut[8];
    __shared__ int sLast;
    __shared__ unsigned char sF[24];
    __shared__ double wRed[5];

    const int tid = threadIdx.x;
    const int c   = tid % 40;
    const bool rg3 = (tid / 40) == 3;
    const bool c39 = (c == 39);

    if (tid < 6) sX[tid] = 0.0f;
    __syncthreads();

    // ---- boundary-end sampling (blocks 0..23; one extra round trip) ----
    if (blockIdx.x < 24) {
        int b    = blockIdx.x / 6;
        int r    = blockIdx.x % 6;
        int ax   = r >> 1;               // 0=D, 1=H, 2=W
        int side = r & 1;                // 0=low end, 1=high end
        int plane, quad;
        if (ax == 0) {                   // fg with d in {0..3} / {156..159}
            int d = (side ? 156 : 0) + (tid & 3);
            plane = b * S + d;
            quad  = (tid * 41) % PLANE4;
        } else if (ax == 1) {            // fg with h in {0..3} / {156..159}
            plane = b * S + (tid % S);
            quad  = (side ? 6240 : 0) + ((tid * 37) % 160);
        } else {                         // fg with w in {0..3} / {156..159}
            plane = b * S + (tid % S);
            quad  = ((tid * 13) % 160) * 40 + (side ? 39 : 0);
        }
        int4 v = ((const int4*)mask)[(size_t)plane * PLANE4 + quad];
        int found = __syncthreads_or(v.x | v.y | v.z | v.w);
        if (tid == 0 && found) g_end[b][r] = 1;
    }

    // ---- streaming pass: 2 pair-bodies, 20 loads in flight each ----
    float aAll = 0.0f, aW = 0.0f;
    #pragma unroll
    for (int j = 0; j < 2; j++) {
        const int cA = blockIdx.x + (2 * j) * NBLK;
        const int cB = cA + NBLK;
        const float4* PA = (const float4*)pred  + (cA >> 3) * PLANE4 + (cA & 7) * CHUNK4 + tid;
        const float4* TA = (const float4*)truth + (cA >> 3) * PLANE4 + (cA & 7) * CHUNK4 + tid;
        const float4* PB = (const float4*)pred  + (cB >> 3) * PLANE4 + (cB & 7) * CHUNK4 + tid;
        const float4* TB = (const float4*)truth + (cB >> 3) * PLANE4 + (cB & 7) * CHUNK4 + tid;

        float qaA = 0.0f, qcA = 0.0f, q4A = 0.0f, w24A = 0.0f;
        float qaB = 0.0f, qcB = 0.0f, q4B = 0.0f, w24B = 0.0f;
        #pragma unroll
        for (int k = 0; k < 5; k++) {
            float4 pa = PA[160 * k];
            float4 ta = TA[160 * k];
            float4 pb = PB[160 * k];
            float4 tb = TB[160 * k];

            float ax_ = pa.x - ta.x, ay = pa.y - ta.y;
            float az  = pa.z - ta.z, aw = pa.w - ta.w;
            float qA = ax_ * ax_;
            qA = fmaf(ay, ay, qA);
            qA = fmaf(az, az, qA);
            float w2A = aw * aw;
            qA += w2A;
            qaA += qA;
            if (c39) qcA += w2A;
            if (k == 4) { q4A = qA; w24A = w2A; }

            float bx_ = pb.x - tb.x, by = pb.y - tb.y;
            float bz  = pb.z - tb.z, bw = pb.w - tb.w;
            float qB = bx_ * bx_;
            qB = fmaf(by, by, qB);
            qB = fmaf(bz, bz, qB);
            float w2B = bw * bw;
            qB += w2B;
            qaB += qB;
            if (c39) qcB += w2B;
            if (k == 4) { q4B = qB; w24B = w2B; }
        }
        aAll += qaA + qaB;
        if (c39) aW += qcA + qcB;
        slab_terms(cA, rg3, c39, qaA, qcA, q4A, w24A, sX);
        slab_terms(cB, rg3, c39, qaB, qcB, q4B, w24B, sX);
    }

    // ---- block reduce; publish 8 values via global double atomics ----
    #pragma unroll
    for (int off = 16; off > 0; off >>= 1) {
        aAll += __shfl_xor_sync(0xFFFFFFFFu, aAll, off);
        aW   += __shfl_xor_sync(0xFFFFFFFFu, aW,   off);
    }
    const int lane = tid & 31, wid = tid >> 5;
    __shared__ float wA[5], wW[5];
    if (lane == 0) { wA[wid] = aAll; wW[wid] = aW; }
    __syncthreads();
    if (tid == 0) {
        float sa = 0.0f, sw = 0.0f;
        #pragma unroll
        for (int w = 0; w < 5; w++) { sa += wA[w]; sw += wW[w]; }
        sOut[0] = (double)sa;            // All
        sOut[1] = (double)sX[0];         // D
        sOut[2] = (double)sX[4];         // H
        sOut[3] = (double)sw;            // W
        sOut[4] = (double)sX[1];         // DH
        sOut[5] = (double)sX[2];         // DW
        sOut[6] = (double)sX[5];         // HW
        sOut[7] = (double)sX[3];         // DHW
    }
    __syncthreads();
    if (tid < 8) atomicAdd(&g_ss8[tid], sOut[tid]);

    // ---- threadFenceReduction ticket: last-done block finalizes ----
    __threadfence();
    __syncthreads();
    if (tid == 0) sLast = (atomicAdd(&g_done, 1u) == (unsigned)(NBLK - 1));
    __syncthreads();
    if (!sLast) return;

    if (tid < 24) sF[tid] = ((volatile unsigned char*)g_end)[tid];
    __syncthreads();
    int ok = 1;
    #pragma unroll
    for (int i = 0; i < 24; i++) ok &= sF[i];

    if (ok) {
        if (tid < 8) sOut[tid] = g_ss8[tid];
        __syncthreads();
        if (tid == 0) {
            double ssOut = sOut[1] + sOut[2] + sOut[3]
                         - sOut[4] - sOut[5] - sOut[6] + sOut[7];
            out[0] = (float)((sOut[0] - 0.99 * ssOut) / TOTAL_ELEMS);
        }
    } else {
        // ---- exact single-block fallback (correct for ARBITRARY masks) ----
        __shared__ int sMn[12], sMx[12];
        if (tid < 12) { sMn[tid] = S; sMx[tid] = -1; }
        __syncthreads();

        const int4* MM = (const int4*)mask;
        for (int i = tid; i < N4; i += NT) {
            int4 v = MM[i];
            if (v.x | v.y | v.z | v.w) {
                int bb  = i / BATCH4;
                int rem = i - bb * BATCH4;
                int d   = rem / PLANE4;
                int ip  = rem - d * PLANE4;
                int h   = ip / 40;
                int w0  = (ip - h * 40) * 4;
                atomicMin(&sMn[bb * 3 + 0], d); atomicMax(&sMx[bb * 3 + 0], d);
                atomicMin(&sMn[bb * 3 + 1], h); atomicMax(&sMx[bb * 3 + 1], h);
                if (v.x) { atomicMin(&sMn[bb * 3 + 2], w0 + 0); atomicMax(&sMx[bb * 3 + 2], w0 + 0); }
                if (v.y) { atomicMin(&sMn[bb * 3 + 2], w0 + 1); atomicMax(&sMx[bb * 3 + 2], w0 + 1); }
                if (v.z) { atomicMin(&sMn[bb * 3 + 2], w0 + 2); atomicMax(&sMx[bb * 3 + 2], w0 + 2); }
                if (v.w) { atomicMin(&sMn[bb * 3 + 2], w0 + 3); atomicMax(&sMx[bb * 3 + 2], w0 + 3); }
            }
        }
        __syncthreads();

        __shared__ int sLo[12], sHi[12];
        if (tid < 12) {
            int mn = (sMx[tid] >= 0) ? sMn[tid] : -1;
            int lo, hi;
            bbox_from(mn, sMx[tid], &lo, &hi);
            sLo[tid] = lo; sHi[tid] = hi;
        }
        __syncthreads();

        const float4* PP = (const float4*)pred;
        const float4* TT = (const float4*)truth;
        float fa = 0.0f;
        for (int i = tid; i < N4; i += NT) {
            float4 pv = PP[i];
            float4 tv = TT[i];
            int bb  = i / BATCH4;
            int rem = i - bb * BATCH4;
            int d   = rem / PLANE4;
            int ip  = rem - d * PLANE4;
            int h   = ip / 40;
            int w0  = (ip - h * 40) * 4;
            bool inDH = (d >= sLo[bb * 3]) && (d < sHi[bb * 3]) &&
                        (h >= sLo[bb * 3 + 1]) && (h < sHi[bb * 3 + 1]);
            int loW = sLo[bb * 3 + 2], hiW = sHi[bb * 3 + 2];
            float wx = (inDH && w0 + 0 >= loW && w0 + 0 < hiW) ? 1.0f : 0.01f;
            float wy = (inDH && w0 + 1 >= loW && w0 + 1 < hiW) ? 1.0f : 0.01f;
            float wz = (inDH && w0 + 2 >= loW && w0 + 2 < hiW) ? 1.0f : 0.01f;
            float ww = (inDH && w0 + 3 >= loW && w0 + 3 < hiW) ? 1.0f : 0.01f;
            float dx = pv.x - tv.x, dy = pv.y - tv.y, dz = pv.z - tv.z, dw = pv.w - tv.w;
            fa = fmaf(wx * dx, dx, fa);
            fa = fmaf(wy * dy, dy, fa);
            fa = fmaf(wz * dz, dz, fa);
            fa = fmaf(ww * dw, dw, fa);
        }
        #pragma unroll
        for (int off = 16; off > 0; off >>= 1)
            fa += __shfl_xor_sync(0xFFFFFFFFu, fa, off);
        if (lane == 0) wRed[wid] = (double)fa;
        __syncthreads();
        if (tid == 0) {
            double s = 0.0;
            #pragma unroll
            for (int w = 0; w < 5; w++) s += wRed[w];
            out[0] = (float)(s / TOTAL_ELEMS);
        }
    }

    // ---- reset scratch so the next graph replay starts from a clean state --
    __syncthreads();
    if (tid < 24) ((unsigned char*)g_end)[tid] = 0;
    if (tid < 8)  g_ss8[tid] = 0.0;
    if (tid == 0) g_done = 0u;
}

extern "C" void kernel_launch(void* const* d_in, const int* in_sizes, int n_in,
                              void* d_out, int out_size) {
    const float* y_pred = (const float*)d_in[0];
    const float* y_true = (const float*)d_in[1];
    const int*   mask   = (const int*)d_in[2];
    float* out = (float*)d_out;

    k_all<<<NBLK, NT>>>(y_pred, y_true, mask, out);
}